// round 5
// baseline (speedup 1.0000x reference)
#include <cuda_runtime.h>
#include <cstdint>

#define BB 256      // batch
#define OO 128      // positions / out features
#define DD 128      // per-position feat
#define IIN (OO*DD) // 16384
#define EIGEN_KC 248  // Eigen threaded gebp depth panel: min((16K-192)/64,320) & ~7

// Scratch (allocation-free rule: __device__ globals)
__device__ float    g_T[(size_t)BB*OO*OO];   // T[b][pos][o], 16.8 MB
__device__ float    g_G[(size_t)OO*BB*OO];   // G[j][b][o] gumbel noise, 16.8 MB
__device__ uint32_t g_keys[OO][2];           // per-step threefry keys

// ---------------- Threefry2x32 (bit-exact JAX, partitionable) ----------------
__device__ __forceinline__ uint32_t rotl32(uint32_t x, int d) {
    return (x << d) | (x >> (32 - d));
}

__device__ __forceinline__ void tf2x32(uint32_t k0, uint32_t k1,
                                       uint32_t x0, uint32_t x1,
                                       uint32_t& o0, uint32_t& o1) {
    uint32_t k2 = k0 ^ k1 ^ 0x1BD11BDAu;
    x0 += k0; x1 += k1;
#define TF_R(r) { x0 += x1; x1 = rotl32(x1, r); x1 ^= x0; }
    TF_R(13) TF_R(15) TF_R(26) TF_R(6)
    x0 += k1;  x1 += k2 + 1u;
    TF_R(17) TF_R(29) TF_R(16) TF_R(24)
    x0 += k2;  x1 += k0 + 2u;
    TF_R(13) TF_R(15) TF_R(26) TF_R(6)
    x0 += k0;  x1 += k1 + 3u;
    TF_R(17) TF_R(29) TF_R(16) TF_R(24)
    x0 += k1;  x1 += k2 + 4u;
    TF_R(13) TF_R(15) TF_R(26) TF_R(6)
    x0 += k2;  x1 += k0 + 5u;
#undef TF_R
    o0 = x0; o1 = x1;
}

__device__ __forceinline__ float bits_to_gumbel(uint32_t bits) {
    float f = __uint_as_float((bits >> 9) | 0x3F800000u) - 1.0f;
    float u = fmaxf(1.17549435e-38f, f);
    double t = -log((double)u);
    return (float)(-log(t));
}

// keys[j] = threefry(key=(0,42), x=(0, j))  [counter-mode split]
__global__ __launch_bounds__(128) void k_keys() {
    int j = threadIdx.x;
    uint32_t o0, o1;
    tf2x32(0u, 42u, 0u, (uint32_t)j, o0, o1);
    g_keys[j][0] = o0;
    g_keys[j][1] = o1;
}

// 32-bit draw for flat index i under keys[j]: out0 ^ out1 of threefry(keys[j], (0, i))
__global__ __launch_bounds__(256) void k_gumbel() {
    int i = blockIdx.x * 256 + threadIdx.x;   // flat element 0..32767 (b*128+o)
    int j = blockIdx.y;                        // step 0..127
    uint32_t o0, o1;
    tf2x32(g_keys[j][0], g_keys[j][1], 0u, (uint32_t)i, o0, o1);
    g_G[(size_t)j * (BB * OO) + i] = bits_to_gumbel(o0 ^ o1);
}

// ---------------- per-position contribution matrix ----------------
// T[b][pos][o] = sum_d enc[b,pos,d] * W[o, pos*128+d]
__global__ __launch_bounds__(256) void k_T(const float* __restrict__ enc,
                                           const float* __restrict__ W) {
    extern __shared__ float sm[];
    float* Wt = sm;                 // [128][129]
    float* E  = sm + 128 * 129;     // [32][128]
    const int pos = blockIdx.x;
    const int b0  = blockIdx.y * 32;
    const int t   = threadIdx.x;

    for (int i = t; i < 128 * 128; i += 256) {
        int o = i >> 7, d = i & 127;
        Wt[d * 129 + o] = W[(size_t)o * IIN + pos * 128 + d];
    }
    for (int i = t; i < 32 * 128; i += 256) {
        int bb = i >> 7, d = i & 127;
        E[i] = enc[(size_t)(b0 + bb) * IIN + pos * 128 + d];
    }
    __syncthreads();

    const int o  = t & 127;
    const int bg = t >> 7;
    float acc[16];
#pragma unroll
    for (int k = 0; k < 16; k++) acc[k] = 0.f;
    for (int d = 0; d < 128; d++) {
        float w = Wt[d * 129 + o];
#pragma unroll
        for (int k = 0; k < 16; k++)
            acc[k] += E[(bg * 16 + k) * 128 + d] * w;
    }
#pragma unroll
    for (int k = 0; k < 16; k++) {
        int b = b0 + bg * 16 + k;
        g_T[((size_t)b * 128 + pos) * 128 + o] = acc[k];
    }
}

// Eigen-gebp (threaded-branch) fp32 emulation of reference p[b,o]:
// depth panels of EIGEN_KC; each panel accumulated serially (FMA, k ascending)
// from zero; C += panel in fp32 ascending panel order. Masked positions
// contribute exact +/-0 FMAs (skipped — bit-identical).
__device__ __noinline__ float emulate_p_fp32(const float* __restrict__ enc_b,
                                             const float* __restrict__ W_o,
                                             const unsigned char* s_mask,
                                             float bias_o) {
    float total = 0.f;
    for (int k0 = 0; k0 < IIN; k0 += EIGEN_KC) {
        int k1 = k0 + EIGEN_KC; if (k1 > IIN) k1 = IIN;
        float acc = 0.f;
        int k = k0;
        while (k < k1) {
            int pos = k >> 7;
            int pe  = (pos + 1) << 7; if (pe > k1) pe = k1;
            if (s_mask[pos]) {
                for (; k < pe; k++)
                    acc = fmaf(enc_b[k], W_o[k], acc);
            } else {
                k = pe;
            }
        }
        total += acc;
    }
    return total + bias_o;
}

// ---------------- persistent per-row decode loop ----------------
__global__ __launch_bounds__(128) void k_decode(const float* __restrict__ enc,
                                                const float* __restrict__ W,
                                                const float* __restrict__ bias,
                                                float* __restrict__ out,
                                                int out_size) {
    const int b = blockIdx.x;
    const int t = threadIdx.x;
    const int lane = t & 31, w = t >> 5;

    __shared__ unsigned long long s_key[128];
    __shared__ unsigned long long s_key2[128];
    __shared__ float  s_pf[128];
    __shared__ double s_pd[128];
    __shared__ double s_max[4];
    __shared__ double s_sum[4];
    __shared__ double s_av[4];
    __shared__ int    s_ai[4];
    __shared__ unsigned char s_mask[128];
    __shared__ unsigned char s_incl[128];
    __shared__ float  s_pj;
    __shared__ int    s_mj;
    __shared__ int    s_errsh;

    const float* enc_b = enc + (size_t)b * IIN;

    // p0 = bias + sum_pos T[b,pos,t] (fp64 accumulation ~= true)
    double pd = (double)bias[t];
    {
        const float* Tb = &g_T[(size_t)b * OO * OO + t];
        double a0 = 0, a1 = 0, a2 = 0, a3 = 0;
#pragma unroll 4
        for (int pos = 0; pos < 128; pos += 4) {
            a0 += (double)Tb[(pos + 0) * 128];
            a1 += (double)Tb[(pos + 1) * 128];
            a2 += (double)Tb[(pos + 2) * 128];
            a3 += (double)Tb[(pos + 3) * 128];
        }
        pd += (a0 + a1) + (a2 + a3);
    }

    int    mval    = 1;
    double ls_sum  = 0.0;
    int    err_sum = 0;
    s_mask[t] = 1;

    const float EPS = 1e-4f;   // tie-cluster window (>> ref fp32 GEMM deviation ~1e-5)

    for (int j = 0; j < 128; j++) {
        float g = g_G[((size_t)j * BB + b) * 128 + t];

        // ranking key: descending fp32 value, ascending index (stable argsort(-p))
        float pf = (float)pd;
        uint32_t fb = __float_as_uint(pf);
        uint32_t ov = (fb & 0x80000000u) ? ~fb : (fb | 0x80000000u);
        unsigned long long key =
            ((unsigned long long)ov << 32) | (unsigned)(127 - t);
        s_key[t] = key;
        s_pd[t]  = pd;
        s_pf[t]  = pf;

        // warp-level masked max (pm = masked ? -9e15 : p)
        double mv = mval ? pd : -9.0e15;
#pragma unroll
        for (int off = 16; off; off >>= 1)
            mv = fmax(mv, __shfl_xor_sync(0xffffffffu, mv, off));
        if (lane == 0) s_max[w] = mv;
        __syncthreads();

        // rank by counting (keys unique -> exactly one thread has cnt == j)
        int cnt = 0;
#pragma unroll 16
        for (int i = 0; i < 128; i++) cnt += (s_key[i] > key);
        if (cnt == j) { s_pj = pf; s_mj = mval; }

        double m = fmax(fmax(s_max[0], s_max[1]), fmax(s_max[2], s_max[3]));

        // sum of exp(pm - m); masked contribute exactly 0
        double ex = mval ? (double)expf((float)(pd - m)) : 0.0;
        double sv = ex;
#pragma unroll
        for (int off = 16; off; off >>= 1)
            sv += __shfl_xor_sync(0xffffffffu, sv, off);
        if (lane == 0) s_sum[w] = sv;

        // gumbel argmax over unmasked of (p + g); ties -> smallest index
        double av = mval ? (pd + (double)g) : -1.0e300;
        int    ai = t;
#pragma unroll
        for (int off = 16; off; off >>= 1) {
            double o_v = __shfl_xor_sync(0xffffffffu, av, off);
            int    o_i = __shfl_xor_sync(0xffffffffu, ai, off);
            if (o_v > av || (o_v == av && o_i < ai)) { av = o_v; ai = o_i; }
        }
        if (lane == 0) { s_av[w] = av; s_ai[w] = ai; }
        __syncthreads();

        // ---- error probe with near-tie resolution ----
        int errj;
        {
            bool incl  = fabsf(pf - s_pj) < EPS;
            if (t == 0) s_errsh = (s_mj == 0) ? 1 : 0;   // default = fast-path answer
            int  mixed = __syncthreads_or(incl && (mval != s_mj));
            if (!mixed) {
                errj = (s_mj == 0) ? 1 : 0;
            } else {
                // resolve cluster order with Eigen-chunked fp32 reference emulation
                s_incl[t] = incl ? 1 : 0;
                unsigned long long key2 = 0;
                if (incl) {
                    float ev = emulate_p_fp32(enc_b, W + (size_t)t * IIN,
                                              s_mask, bias[t]);
                    uint32_t eb = __float_as_uint(ev);
                    uint32_t eo = (eb & 0x80000000u) ? ~eb : (eb | 0x80000000u);
                    key2 = ((unsigned long long)eo << 32) | (unsigned)(127 - t);
                }
                s_key2[t] = key2;
                __syncthreads();
                if (incl) {
                    int cm = 0;
                    for (int i = 0; i < 128; i++) {
                        if (s_incl[i]) cm += (s_key2[i] > key2);
                        else           cm += (s_pf[i] > s_pj);
                    }
                    if (cm == j) s_errsh = (mval == 0) ? 1 : 0;
                }
                __syncthreads();
                errj = s_errsh;
            }
        }

        double ssum = s_sum[0] + s_sum[1] + s_sum[2] + s_sum[3];
        double lse  = m + log(ssum);

        double bv = s_av[0]; int bi = s_ai[0];
#pragma unroll
        for (int k = 1; k < 4; k++) {
            if (s_av[k] > bv || (s_av[k] == bv && s_ai[k] < bi)) {
                bv = s_av[k]; bi = s_ai[k];
            }
        }
        const int pos = bi;

        if (t == pos) mval = 0;
        __syncthreads();
        if (t == pos) s_mask[pos] = 0;
        if (t == 0) {
            ls_sum  += s_pd[pos] - lse;
            err_sum += errj;
            if (out_size >= BB * OO)
                out[b * 128 + (127 - j)] = (float)pos;  // flipped column order
        }

        // incremental update: remove chosen position's contribution
        pd -= (double)g_T[((size_t)b * 128 + pos) * 128 + t];
        __syncthreads();
    }

    if (t == 0) {
        if (out_size >= BB * OO + 2 * BB) {
            out[BB * OO + b]      = (float)ls_sum;
            out[BB * OO + BB + b] = (float)err_sum;
        } else if (out_size >= BB * OO + BB) {
            out[BB * OO + b] = (float)ls_sum;
        }
    }
}

// ---------------- launch ----------------
extern "C" void kernel_launch(void* const* d_in, const int* in_sizes, int n_in,
                              void* d_out, int out_size) {
    const float* enc  = (const float*)d_in[0];   // [256,128,128]
    const float* W    = (const float*)d_in[1];   // [128,16384]
    const float* bias = (const float*)d_in[2];   // [128]
    float* out = (float*)d_out;

    const int smemT = (128 * 129 + 32 * 128) * (int)sizeof(float);  // 82432 B
    cudaFuncSetAttribute(k_T, cudaFuncAttributeMaxDynamicSharedMemorySize, smemT);

    k_keys<<<1, 128>>>();
    k_T<<<dim3(128, 8), 256, smemT>>>(enc, W);
    k_gumbel<<<dim3(128, 128), 256>>>();
    k_decode<<<256, 128>>>(enc, W, bias, out, out_size);
}

// round 6
// speedup vs baseline: 2.1784x; 2.1784x over previous
#include <cuda_runtime.h>
#include <cstdint>

#define BB 256      // batch
#define OO 128      // positions / out features
#define DD 128      // per-position feat
#define IIN (OO*DD) // 16384
#define EIGEN_KC 248  // Eigen threaded gebp depth panel (validated R5)

// Scratch (allocation-free rule: __device__ globals)
__device__ float    g_T[(size_t)BB*OO*OO];   // T[b][pos][o], 16.8 MB
__device__ float    g_G[(size_t)OO*BB*OO];   // G[j][b][o] gumbel noise, 16.8 MB
__device__ uint32_t g_keys[OO][2];           // per-step threefry keys

// ---------------- Threefry2x32 (bit-exact JAX, partitionable) ----------------
__device__ __forceinline__ uint32_t rotl32(uint32_t x, int d) {
    return (x << d) | (x >> (32 - d));
}

__device__ __forceinline__ void tf2x32(uint32_t k0, uint32_t k1,
                                       uint32_t x0, uint32_t x1,
                                       uint32_t& o0, uint32_t& o1) {
    uint32_t k2 = k0 ^ k1 ^ 0x1BD11BDAu;
    x0 += k0; x1 += k1;
#define TF_R(r) { x0 += x1; x1 = rotl32(x1, r); x1 ^= x0; }
    TF_R(13) TF_R(15) TF_R(26) TF_R(6)
    x0 += k1;  x1 += k2 + 1u;
    TF_R(17) TF_R(29) TF_R(16) TF_R(24)
    x0 += k2;  x1 += k0 + 2u;
    TF_R(13) TF_R(15) TF_R(26) TF_R(6)
    x0 += k0;  x1 += k1 + 3u;
    TF_R(17) TF_R(29) TF_R(16) TF_R(24)
    x0 += k1;  x1 += k2 + 4u;
    TF_R(13) TF_R(15) TF_R(26) TF_R(6)
    x0 += k2;  x1 += k0 + 5u;
#undef TF_R
    o0 = x0; o1 = x1;
}

__device__ __forceinline__ float bits_to_gumbel(uint32_t bits) {
    // fp32 path (matches XLA fp32 log to ~2ulp; revert to double-log if positions break)
    float f = __uint_as_float((bits >> 9) | 0x3F800000u) - 1.0f;
    float u = fmaxf(1.17549435e-38f, f);
    float t = -logf(u);
    return -logf(t);
}

// keys[j] = threefry(key=(0,42), x=(0, j))  [counter-mode split]
__global__ __launch_bounds__(128) void k_keys() {
    int j = threadIdx.x;
    uint32_t o0, o1;
    tf2x32(0u, 42u, 0u, (uint32_t)j, o0, o1);
    g_keys[j][0] = o0;
    g_keys[j][1] = o1;
}

// 32-bit draw for flat index i under keys[j]: out0 ^ out1 of threefry(keys[j], (0, i))
__global__ __launch_bounds__(256) void k_gumbel() {
    int i = blockIdx.x * 256 + threadIdx.x;   // flat element 0..32767 (b*128+o)
    int j = blockIdx.y;                        // step 0..127
    uint32_t o0, o1;
    tf2x32(g_keys[j][0], g_keys[j][1], 0u, (uint32_t)i, o0, o1);
    g_G[(size_t)j * (BB * OO) + i] = bits_to_gumbel(o0 ^ o1);
}

// ---------------- per-position contribution matrix ----------------
// T[b][pos][o] = sum_d enc[b,pos,d] * W[o, pos*128+d]
__global__ __launch_bounds__(256) void k_T(const float* __restrict__ enc,
                                           const float* __restrict__ W) {
    extern __shared__ float sm[];
    float* Wt = sm;                 // [128][129]
    float* E  = sm + 128 * 129;     // [32][128]
    const int pos = blockIdx.x;
    const int b0  = blockIdx.y * 32;
    const int t   = threadIdx.x;

    for (int i = t; i < 128 * 128; i += 256) {
        int o = i >> 7, d = i & 127;
        Wt[d * 129 + o] = W[(size_t)o * IIN + pos * 128 + d];
    }
    for (int i = t; i < 32 * 128; i += 256) {
        int bb = i >> 7, d = i & 127;
        E[i] = enc[(size_t)(b0 + bb) * IIN + pos * 128 + d];
    }
    __syncthreads();

    const int o  = t & 127;
    const int bg = t >> 7;
    float acc[16];
#pragma unroll
    for (int k = 0; k < 16; k++) acc[k] = 0.f;
    for (int d = 0; d < 128; d++) {
        float w = Wt[d * 129 + o];
#pragma unroll
        for (int k = 0; k < 16; k++)
            acc[k] += E[(bg * 16 + k) * 128 + d] * w;
    }
#pragma unroll
    for (int k = 0; k < 16; k++) {
        int b = b0 + bg * 16 + k;
        g_T[((size_t)b * 128 + pos) * 128 + o] = acc[k];
    }
}

// Eigen-gebp (threaded) fp32 emulation of reference p[b,o] (validated R5).
__device__ __noinline__ float emulate_p_fp32(const float* __restrict__ enc_b,
                                             const float* __restrict__ W_o,
                                             const unsigned char* s_mask,
                                             float bias_o) {
    float total = 0.f;
    for (int k0 = 0; k0 < IIN; k0 += EIGEN_KC) {
        int k1 = k0 + EIGEN_KC; if (k1 > IIN) k1 = IIN;
        float acc = 0.f;
        int k = k0;
        while (k < k1) {
            int pos = k >> 7;
            int pe  = (pos + 1) << 7; if (pe > k1) pe = k1;
            if (s_mask[pos]) {
                for (; k < pe; k++)
                    acc = fmaf(enc_b[k], W_o[k], acc);
            } else {
                k = pe;
            }
        }
        total += acc;
    }
    return total + bias_o;
}

__device__ __forceinline__ uint32_t ord32(float f) {
    uint32_t fb = __float_as_uint(f);
    return (fb & 0x80000000u) ? ~fb : (fb | 0x80000000u);
}
__device__ __forceinline__ float unord32(uint32_t u) {
    return __uint_as_float((u & 0x80000000u) ? (u & 0x7FFFFFFFu) : ~u);
}
__device__ __forceinline__ unsigned long long ord64(double d) {
    unsigned long long ub = (unsigned long long)__double_as_longlong(d);
    return (ub & 0x8000000000000000ULL) ? ~ub : (ub | 0x8000000000000000ULL);
}

// ---------------- persistent per-row decode loop ----------------
// Dynamic smem layout:
//   [0,      65536)  sT      : T[b] tile, 128x128 fp32
//   [65536,  66560)  s_key   : 128 x u64 rank keys   (reused post-loop as double[128])
//   [66560,  67584)  s_key2  : resolver keys
//   [67584,  68096)  s_pf    : 128 x fp32
//   [68096,  68224)  s_incl  : 128 x u8
#define SMEM_DECODE 68224

__global__ __launch_bounds__(128) void k_decode(const float* __restrict__ enc,
                                                const float* __restrict__ W,
                                                const float* __restrict__ bias,
                                                float* __restrict__ out,
                                                int out_size) {
    extern __shared__ char dsm[];
    float* sT = (float*)dsm;
    unsigned long long* s_key  = (unsigned long long*)(dsm + 65536);
    unsigned long long* s_key2 = (unsigned long long*)(dsm + 66560);
    float* s_pf = (float*)(dsm + 67584);
    unsigned char* s_incl = (unsigned char*)(dsm + 68096);

    __shared__ uint32_t s_wmax[4];
    __shared__ float    s_wsum[4];
    __shared__ unsigned long long s_wav[4];
    __shared__ int      s_wai[4];
    __shared__ unsigned char s_mask[128];
    __shared__ float    s_pj;
    __shared__ int      s_mj;
    __shared__ int      s_errsh;

    const int b = blockIdx.x;
    const int t = threadIdx.x;
    const int lane = t & 31, w = t >> 5;
    const float* enc_b = enc + (size_t)b * IIN;
    const float* Tg = &g_T[(size_t)b * OO * OO];

    // stage T[b] into smem (coalesced float4)
    {
        const float4* src = (const float4*)Tg;
        float4* dst = (float4*)sT;
#pragma unroll
        for (int i = 0; i < 32; i++)
            dst[i * 128 + t] = src[i * 128 + t];
    }
    s_mask[t] = 1;
    __syncthreads();

    // p0 = bias + sum_pos T[b,pos,t] (fp64, matches validated init)
    double pd = (double)bias[t];
    {
        double a0 = 0, a1 = 0, a2 = 0, a3 = 0;
#pragma unroll 4
        for (int pos = 0; pos < 128; pos += 4) {
            a0 += (double)sT[(pos + 0) * 128 + t];
            a1 += (double)sT[(pos + 1) * 128 + t];
            a2 += (double)sT[(pos + 2) * 128 + t];
            a3 += (double)sT[(pos + 3) * 128 + t];
        }
        pd += (a0 + a1) + (a2 + a3);
    }

    int   mval    = 1;
    int   err_sum = 0;
    float r_m = 0.f, r_ssum = 1.f, r_pch = 0.f;   // per-step stats held by thread t==j

    const float EPS = 1e-4f;
    float g_cur = g_G[(size_t)b * 128 + t];       // j = 0

    for (int j = 0; j < 128; j++) {
        // prefetch next step's gumbel (off the critical chain)
        float g_nxt = 0.f;
        if (j < 127) g_nxt = g_G[((size_t)(j + 1) * BB + b) * 128 + t];

        float pf = (float)pd;
        uint32_t ov = ord32(pf);
        unsigned long long key =
            ((unsigned long long)ov << 32) | (unsigned)(127 - t);
        s_key[t] = key;
        s_pf[t]  = pf;

        // warp masked max (ordered-u32 integer max; 0 = sentinel below all reals)
        uint32_t mm = mval ? ov : 0u;
#pragma unroll
        for (int off = 16; off; off >>= 1)
            mm = max(mm, __shfl_xor_sync(0xffffffffu, mm, off));
        if (lane == 0) s_wmax[w] = mm;

        // gumbel argmax key (ordered-u64); ties -> smallest index
        double av = pd + (double)g_cur;
        unsigned long long au = mval ? ord64(av) : 0ULL;
        int ai = t;
#pragma unroll
        for (int off = 16; off; off >>= 1) {
            unsigned long long o_u = __shfl_xor_sync(0xffffffffu, au, off);
            int o_i = __shfl_xor_sync(0xffffffffu, ai, off);
            if (o_u > au || (o_u == au && o_i < ai)) { au = o_u; ai = o_i; }
        }
        if (lane == 0) { s_wav[w] = au; s_wai[w] = ai; }
        __syncthreads();   // A

        // final argmax (all threads, uniform)
        unsigned long long bv = s_wav[0]; int bi = s_wai[0];
#pragma unroll
        for (int k = 1; k < 4; k++) {
            if (s_wav[k] > bv || (s_wav[k] == bv && s_wai[k] < bi)) {
                bv = s_wav[k]; bi = s_wai[k];
            }
        }
        const int pos = bi;

        // softmax pieces (fp32)
        uint32_t mu = max(max(s_wmax[0], s_wmax[1]), max(s_wmax[2], s_wmax[3]));
        float m_f = unord32(mu);
        float ex = mval ? expf(pf - m_f) : 0.f;
        float sv = ex;
#pragma unroll
        for (int off = 16; off; off >>= 1)
            sv += __shfl_xor_sync(0xffffffffu, sv, off);
        if (lane == 0) s_wsum[w] = sv;

        // rank-by-counting (vectorized over pairs of u64 keys)
        int cnt = 0;
        {
            const ulonglong2* k2 = (const ulonglong2*)s_key;
#pragma unroll 16
            for (int i = 0; i < 64; i++) {
                ulonglong2 v = k2[i];
                cnt += (v.x > key) + (v.y > key);
            }
        }
        if (cnt == j) { s_pj = pf; s_mj = mval; }
        __syncthreads();   // B1

        float ssum = (s_wsum[0] + s_wsum[1]) + (s_wsum[2] + s_wsum[3]);
        if (t == j) { r_m = m_f; r_ssum = ssum; r_pch = s_pf[pos]; }

        // ---- error probe with near-tie resolution ----
        bool incl = fabsf(pf - s_pj) < EPS;
        if (t == 0) s_errsh = (s_mj == 0) ? 1 : 0;
        int errj;
        int mixed = __syncthreads_or(incl && (mval != s_mj));   // B2
        if (!mixed) {
            errj = (s_mj == 0) ? 1 : 0;
        } else {
            s_incl[t] = incl ? 1 : 0;
            unsigned long long key2 = 0;
            if (incl) {
                float ev = emulate_p_fp32(enc_b, W + (size_t)t * IIN,
                                          s_mask, bias[t]);
                uint32_t eo = ord32(ev);
                key2 = ((unsigned long long)eo << 32) | (unsigned)(127 - t);
            }
            s_key2[t] = key2;
            __syncthreads();
            if (incl) {
                int cm = 0;
                for (int i = 0; i < 128; i++) {
                    if (s_incl[i]) cm += (s_key2[i] > key2);
                    else           cm += (s_pf[i] > s_pj);
                }
                if (cm == j) s_errsh = (mval == 0) ? 1 : 0;
            }
            __syncthreads();
            errj = s_errsh;
        }

        if (t == 0) {
            err_sum += errj;
            if (out_size >= BB * OO)
                out[b * 128 + (127 - j)] = (float)pos;  // flipped column order
        }
        if (t == pos) { mval = 0; s_mask[t] = 0; }  // next read is after next B2

        // incremental update from staged T (LDS) — critical chain
        pd -= (double)sT[pos * 128 + t];
        g_cur = g_nxt;
    }

    // deferred log-softmax accumulation: thread t holds step-t stats
    {
        double ls_t = (double)r_pch - (double)r_m - log((double)r_ssum);
        double* s_red = (double*)s_key;   // reuse
        s_red[t] = ls_t;
        __syncthreads();
        if (t == 0) {
            double acc = 0.0;
            for (int i = 0; i < 128; i++) acc += s_red[i];
            if (out_size >= BB * OO + 2 * BB) {
                out[BB * OO + b]      = (float)acc;
                out[BB * OO + BB + b] = (float)err_sum;
            } else if (out_size >= BB * OO + BB) {
                out[BB * OO + b] = (float)acc;
            }
        }
    }
}

// ---------------- launch ----------------
extern "C" void kernel_launch(void* const* d_in, const int* in_sizes, int n_in,
                              void* d_out, int out_size) {
    const float* enc  = (const float*)d_in[0];   // [256,128,128]
    const float* W    = (const float*)d_in[1];   // [128,16384]
    const float* bias = (const float*)d_in[2];   // [128]
    float* out = (float*)d_out;

    const int smemT = (128 * 129 + 32 * 128) * (int)sizeof(float);  // 82432 B
    cudaFuncSetAttribute(k_T, cudaFuncAttributeMaxDynamicSharedMemorySize, smemT);
    cudaFuncSetAttribute(k_decode, cudaFuncAttributeMaxDynamicSharedMemorySize,
                         SMEM_DECODE);

    k_keys<<<1, 128>>>();
    k_T<<<dim3(128, 8), 256, smemT>>>(enc, W);
    k_gumbel<<<dim3(128, 128), 256>>>();
    k_decode<<<256, 128, SMEM_DECODE>>>(enc, W, bias, out, out_size);
}

// round 7
// speedup vs baseline: 2.1797x; 1.0006x over previous
#include <cuda_runtime.h>
#include <cstdint>

#define BB 256      // batch
#define OO 128      // positions / out features
#define DD 128      // per-position feat
#define IIN (OO*DD) // 16384
#define EIGEN_KC 248  // Eigen threaded gebp depth panel (validated R5)

// Scratch (allocation-free rule: __device__ globals)
__device__ float    g_T[(size_t)BB*OO*OO];   // T[b][pos][o], 16.8 MB
__device__ float    g_G[(size_t)OO*BB*OO];   // G[j][b][o] gumbel noise, 16.8 MB
__device__ uint32_t g_keys[OO][2];           // per-step threefry keys

// ---------------- Threefry2x32 (bit-exact JAX, partitionable) ----------------
__device__ __forceinline__ uint32_t rotl32(uint32_t x, int d) {
    return (x << d) | (x >> (32 - d));
}

__device__ __forceinline__ void tf2x32(uint32_t k0, uint32_t k1,
                                       uint32_t x0, uint32_t x1,
                                       uint32_t& o0, uint32_t& o1) {
    uint32_t k2 = k0 ^ k1 ^ 0x1BD11BDAu;
    x0 += k0; x1 += k1;
#define TF_R(r) { x0 += x1; x1 = rotl32(x1, r); x1 ^= x0; }
    TF_R(13) TF_R(15) TF_R(26) TF_R(6)
    x0 += k1;  x1 += k2 + 1u;
    TF_R(17) TF_R(29) TF_R(16) TF_R(24)
    x0 += k2;  x1 += k0 + 2u;
    TF_R(13) TF_R(15) TF_R(26) TF_R(6)
    x0 += k0;  x1 += k1 + 3u;
    TF_R(17) TF_R(29) TF_R(16) TF_R(24)
    x0 += k1;  x1 += k2 + 4u;
    TF_R(13) TF_R(15) TF_R(26) TF_R(6)
    x0 += k2;  x1 += k0 + 5u;
#undef TF_R
    o0 = x0; o1 = x1;
}

__device__ __forceinline__ float bits_to_gumbel(uint32_t bits) {
    // fp32 path (matches XLA fp32 log to ~2ulp; revert to double-log if positions break)
    float f = __uint_as_float((bits >> 9) | 0x3F800000u) - 1.0f;
    float u = fmaxf(1.17549435e-38f, f);
    float t = -logf(u);
    return -logf(t);
}

// keys[j] = threefry(key=(0,42), x=(0, j))  [counter-mode split]
__global__ __launch_bounds__(128) void k_keys() {
    int j = threadIdx.x;
    uint32_t o0, o1;
    tf2x32(0u, 42u, 0u, (uint32_t)j, o0, o1);
    g_keys[j][0] = o0;
    g_keys[j][1] = o1;
}

// 32-bit draw for flat index i under keys[j]: out0 ^ out1 of threefry(keys[j], (0, i))
__global__ __launch_bounds__(256) void k_gumbel() {
    int i = blockIdx.x * 256 + threadIdx.x;   // flat element 0..32767 (b*128+o)
    int j = blockIdx.y;                        // step 0..127
    uint32_t o0, o1;
    tf2x32(g_keys[j][0], g_keys[j][1], 0u, (uint32_t)i, o0, o1);
    g_G[(size_t)j * (BB * OO) + i] = bits_to_gumbel(o0 ^ o1);
}

// ---------------- per-position contribution matrix ----------------
// T[b][pos][o] = sum_d enc[b,pos,d] * W[o, pos*128+d]
__global__ __launch_bounds__(256) void k_T(const float* __restrict__ enc,
                                           const float* __restrict__ W) {
    extern __shared__ float sm[];
    float* Wt = sm;                 // [128][129]
    float* E  = sm + 128 * 129;     // [32][128]
    const int pos = blockIdx.x;
    const int b0  = blockIdx.y * 32;
    const int t   = threadIdx.x;

    for (int i = t; i < 128 * 128; i += 256) {
        int o = i >> 7, d = i & 127;
        Wt[d * 129 + o] = W[(size_t)o * IIN + pos * 128 + d];
    }
    for (int i = t; i < 32 * 128; i += 256) {
        int bb = i >> 7, d = i & 127;
        E[i] = enc[(size_t)(b0 + bb) * IIN + pos * 128 + d];
    }
    __syncthreads();

    const int o  = t & 127;
    const int bg = t >> 7;
    float acc[16];
#pragma unroll
    for (int k = 0; k < 16; k++) acc[k] = 0.f;
    for (int d = 0; d < 128; d++) {
        float w = Wt[d * 129 + o];
#pragma unroll
        for (int k = 0; k < 16; k++)
            acc[k] += E[(bg * 16 + k) * 128 + d] * w;
    }
#pragma unroll
    for (int k = 0; k < 16; k++) {
        int b = b0 + bg * 16 + k;
        g_T[((size_t)b * 128 + pos) * 128 + o] = acc[k];
    }
}

// Eigen-gebp (threaded) fp32 emulation of reference p[b,o] (validated R5).
__device__ __noinline__ float emulate_p_fp32(const float* __restrict__ enc_b,
                                             const float* __restrict__ W_o,
                                             const unsigned char* s_mask,
                                             float bias_o) {
    float total = 0.f;
    for (int k0 = 0; k0 < IIN; k0 += EIGEN_KC) {
        int k1 = k0 + EIGEN_KC; if (k1 > IIN) k1 = IIN;
        float acc = 0.f;
        int k = k0;
        while (k < k1) {
            int pos = k >> 7;
            int pe  = (pos + 1) << 7; if (pe > k1) pe = k1;
            if (s_mask[pos]) {
                for (; k < pe; k++)
                    acc = fmaf(enc_b[k], W_o[k], acc);
            } else {
                k = pe;
            }
        }
        total += acc;
    }
    return total + bias_o;
}

__device__ __forceinline__ uint32_t ord32(float f) {
    uint32_t fb = __float_as_uint(f);
    return (fb & 0x80000000u) ? ~fb : (fb | 0x80000000u);
}
__device__ __forceinline__ float unord32(uint32_t u) {
    return __uint_as_float((u & 0x80000000u) ? (u & 0x7FFFFFFFu) : ~u);
}
__device__ __forceinline__ unsigned long long ord64(double d) {
    unsigned long long ub = (unsigned long long)__double_as_longlong(d);
    return (ub & 0x8000000000000000ULL) ? ~ub : (ub | 0x8000000000000000ULL);
}

// ---------------- persistent per-row decode loop ----------------
// Dynamic smem layout:
//   [0,      65536)  sT      : T[b] tile, 128x128 fp32
//   [65536,  66560)  s_key   : 128 x u64 rank keys   (reused post-loop as double[128])
//   [66560,  67584)  s_key2  : resolver keys
//   [67584,  68096)  s_pf    : 128 x fp32
//   [68096,  68224)  s_incl  : 128 x u8
#define SMEM_DECODE 68224

__global__ __launch_bounds__(128) void k_decode(const float* __restrict__ enc,
                                                const float* __restrict__ W,
                                                const float* __restrict__ bias,
                                                float* __restrict__ out,
                                                int out_size) {
    extern __shared__ char dsm[];
    float* sT = (float*)dsm;
    unsigned long long* s_key  = (unsigned long long*)(dsm + 65536);
    unsigned long long* s_key2 = (unsigned long long*)(dsm + 66560);
    float* s_pf = (float*)(dsm + 67584);
    unsigned char* s_incl = (unsigned char*)(dsm + 68096);

    __shared__ uint32_t s_wmax[4];
    __shared__ float    s_wsum[4];
    __shared__ unsigned long long s_wav[4];
    __shared__ int      s_wai[4];
    __shared__ unsigned char s_mask[128];
    __shared__ float    s_pj;
    __shared__ int      s_mj;
    __shared__ int      s_errsh;

    const int b = blockIdx.x;
    const int t = threadIdx.x;
    const int lane = t & 31, w = t >> 5;
    const float* enc_b = enc + (size_t)b * IIN;
    const float* Tg = &g_T[(size_t)b * OO * OO];

    // stage T[b] into smem (coalesced float4)
    {
        const float4* src = (const float4*)Tg;
        float4* dst = (float4*)sT;
#pragma unroll
        for (int i = 0; i < 32; i++)
            dst[i * 128 + t] = src[i * 128 + t];
    }
    s_mask[t] = 1;
    __syncthreads();

    // p0 = bias + sum_pos T[b,pos,t] (fp64, matches validated init)
    double pd = (double)bias[t];
    {
        double a0 = 0, a1 = 0, a2 = 0, a3 = 0;
#pragma unroll 4
        for (int pos = 0; pos < 128; pos += 4) {
            a0 += (double)sT[(pos + 0) * 128 + t];
            a1 += (double)sT[(pos + 1) * 128 + t];
            a2 += (double)sT[(pos + 2) * 128 + t];
            a3 += (double)sT[(pos + 3) * 128 + t];
        }
        pd += (a0 + a1) + (a2 + a3);
    }

    int   mval    = 1;
    int   err_sum = 0;
    float r_m = 0.f, r_ssum = 1.f, r_pch = 0.f;   // per-step stats held by thread t==j

    const float EPS = 1e-4f;
    float g_cur = g_G[(size_t)b * 128 + t];       // j = 0

    for (int j = 0; j < 128; j++) {
        // prefetch next step's gumbel (off the critical chain)
        float g_nxt = 0.f;
        if (j < 127) g_nxt = g_G[((size_t)(j + 1) * BB + b) * 128 + t];

        float pf = (float)pd;
        uint32_t ov = ord32(pf);
        unsigned long long key =
            ((unsigned long long)ov << 32) | (unsigned)(127 - t);
        s_key[t] = key;
        s_pf[t]  = pf;

        // warp masked max (ordered-u32 integer max; 0 = sentinel below all reals)
        uint32_t mm = mval ? ov : 0u;
#pragma unroll
        for (int off = 16; off; off >>= 1)
            mm = max(mm, __shfl_xor_sync(0xffffffffu, mm, off));
        if (lane == 0) s_wmax[w] = mm;

        // gumbel argmax key (ordered-u64); ties -> smallest index
        double av = pd + (double)g_cur;
        unsigned long long au = mval ? ord64(av) : 0ULL;
        int ai = t;
#pragma unroll
        for (int off = 16; off; off >>= 1) {
            unsigned long long o_u = __shfl_xor_sync(0xffffffffu, au, off);
            int o_i = __shfl_xor_sync(0xffffffffu, ai, off);
            if (o_u > au || (o_u == au && o_i < ai)) { au = o_u; ai = o_i; }
        }
        if (lane == 0) { s_wav[w] = au; s_wai[w] = ai; }
        __syncthreads();   // A

        // final argmax (all threads, uniform)
        unsigned long long bv = s_wav[0]; int bi = s_wai[0];
#pragma unroll
        for (int k = 1; k < 4; k++) {
            if (s_wav[k] > bv || (s_wav[k] == bv && s_wai[k] < bi)) {
                bv = s_wav[k]; bi = s_wai[k];
            }
        }
        const int pos = bi;

        // softmax pieces (fp32)
        uint32_t mu = max(max(s_wmax[0], s_wmax[1]), max(s_wmax[2], s_wmax[3]));
        float m_f = unord32(mu);
        float ex = mval ? expf(pf - m_f) : 0.f;
        float sv = ex;
#pragma unroll
        for (int off = 16; off; off >>= 1)
            sv += __shfl_xor_sync(0xffffffffu, sv, off);
        if (lane == 0) s_wsum[w] = sv;

        // rank-by-counting (vectorized over pairs of u64 keys)
        int cnt = 0;
        {
            const ulonglong2* k2 = (const ulonglong2*)s_key;
#pragma unroll 16
            for (int i = 0; i < 64; i++) {
                ulonglong2 v = k2[i];
                cnt += (v.x > key) + (v.y > key);
            }
        }
        if (cnt == j) { s_pj = pf; s_mj = mval; }
        __syncthreads();   // B1

        float ssum = (s_wsum[0] + s_wsum[1]) + (s_wsum[2] + s_wsum[3]);
        if (t == j) { r_m = m_f; r_ssum = ssum; r_pch = s_pf[pos]; }

        // ---- error probe with near-tie resolution ----
        bool incl = fabsf(pf - s_pj) < EPS;
        if (t == 0) s_errsh = (s_mj == 0) ? 1 : 0;
        int errj;
        int mixed = __syncthreads_or(incl && (mval != s_mj));   // B2
        if (!mixed) {
            errj = (s_mj == 0) ? 1 : 0;
        } else {
            s_incl[t] = incl ? 1 : 0;
            unsigned long long key2 = 0;
            if (incl) {
                float ev = emulate_p_fp32(enc_b, W + (size_t)t * IIN,
                                          s_mask, bias[t]);
                uint32_t eo = ord32(ev);
                key2 = ((unsigned long long)eo << 32) | (unsigned)(127 - t);
            }
            s_key2[t] = key2;
            __syncthreads();
            if (incl) {
                int cm = 0;
                for (int i = 0; i < 128; i++) {
                    if (s_incl[i]) cm += (s_key2[i] > key2);
                    else           cm += (s_pf[i] > s_pj);
                }
                if (cm == j) s_errsh = (mval == 0) ? 1 : 0;
            }
            __syncthreads();
            errj = s_errsh;
        }

        if (t == 0) {
            err_sum += errj;
            if (out_size >= BB * OO)
                out[b * 128 + (127 - j)] = (float)pos;  // flipped column order
        }
        if (t == pos) { mval = 0; s_mask[t] = 0; }  // next read is after next B2

        // incremental update from staged T (LDS) — critical chain
        pd -= (double)sT[pos * 128 + t];
        g_cur = g_nxt;
    }

    // deferred log-softmax accumulation: thread t holds step-t stats
    {
        double ls_t = (double)r_pch - (double)r_m - log((double)r_ssum);
        double* s_red = (double*)s_key;   // reuse
        s_red[t] = ls_t;
        __syncthreads();
        if (t == 0) {
            double acc = 0.0;
            for (int i = 0; i < 128; i++) acc += s_red[i];
            if (out_size >= BB * OO + 2 * BB) {
                out[BB * OO + b]      = (float)acc;
                out[BB * OO + BB + b] = (float)err_sum;
            } else if (out_size >= BB * OO + BB) {
                out[BB * OO + b] = (float)acc;
            }
        }
    }
}

// ---------------- launch ----------------
extern "C" void kernel_launch(void* const* d_in, const int* in_sizes, int n_in,
                              void* d_out, int out_size) {
    const float* enc  = (const float*)d_in[0];   // [256,128,128]
    const float* W    = (const float*)d_in[1];   // [128,16384]
    const float* bias = (const float*)d_in[2];   // [128]
    float* out = (float*)d_out;

    const int smemT = (128 * 129 + 32 * 128) * (int)sizeof(float);  // 82432 B
    cudaFuncSetAttribute(k_T, cudaFuncAttributeMaxDynamicSharedMemorySize, smemT);
    cudaFuncSetAttribute(k_decode, cudaFuncAttributeMaxDynamicSharedMemorySize,
                         SMEM_DECODE);

    k_keys<<<1, 128>>>();
    k_T<<<dim3(128, 8), 256, smemT>>>(enc, W);
    k_gumbel<<<dim3(128, 128), 256>>>();
    k_decode<<<256, 128, SMEM_DECODE>>>(enc, W, bias, out, out_size);
}